// round 13
// baseline (speedup 1.0000x reference)
#include <cuda_runtime.h>
#include <cuda_fp16.h>

#define N_NODES 100000
#define N_EDGES 3200000
#define F0 300
#define F0P 304            // padded K for GEMM1 (19 * 16)
#define F1 128
#define F2 64
#define NT1 (F0P / 16)     // 19 k-tiles

#define SCAN_B 1024
#define N_SCANBLK ((N_NODES + SCAN_B - 1) / SCAN_B)   // 98

// ---- scratch (static device allocations; no cudaMalloc allowed) ----
__device__ int    g_deg[N_NODES];
__device__ int    g_off[N_NODES + 1];
__device__ int    g_cur[N_NODES];
__device__ int    g_csr[N_EDGES];
__device__ int    g_bsum[N_SCANBLK];
__device__ int    g_bpre[N_SCANBLK];
__device__ float  g_dinv[N_NODES];
__device__ __half g_y1h[(size_t)N_NODES * F1];   // fp16 message rows, layer 1
__device__ __half g_hh[(size_t)N_NODES * F1];    // hidden, fp16
__device__ __half g_y2h[(size_t)N_NODES * F2];   // fp16 message rows, layer 2
// pre-converted, pre-transposed weights: [n][k] with k contiguous
__device__ __half g_W1T[F1 * F0P];
__device__ __half g_W2T[F2 * F1];

// ---- streams/events for fork-join inside the captured graph ----
static cudaStream_t s_conv, s_csr;
static cudaEvent_t  ev_root, ev_conv, ev_cnt, ev_csr;
struct _InitStreams {
    _InitStreams() {
        cudaStreamCreateWithFlags(&s_conv, cudaStreamNonBlocking);
        cudaStreamCreateWithFlags(&s_csr, cudaStreamNonBlocking);
        cudaEventCreateWithFlags(&ev_root, cudaEventDisableTiming);
        cudaEventCreateWithFlags(&ev_conv, cudaEventDisableTiming);
        cudaEventCreateWithFlags(&ev_cnt, cudaEventDisableTiming);
        cudaEventCreateWithFlags(&ev_csr, cudaEventDisableTiming);
    }
};
static _InitStreams _g_init_streams;

// ---------------- degree ----------------
__global__ void k_zero_deg() {
    int i = blockIdx.x * blockDim.x + threadIdx.x;
    if (i < N_NODES) g_deg[i] = 0;
}

__global__ void k_count(const int* __restrict__ dst) {
    int i = blockIdx.x * blockDim.x + threadIdx.x;
    if (i < N_EDGES) atomicAdd(&g_deg[dst[i]], 1);
}

// ---------------- scan (3 phases; scan1 also computes dinv) ----------------
__global__ void k_scan1() {
    __shared__ int sh[SCAN_B];
    int tid = threadIdx.x;
    int gid = blockIdx.x * SCAN_B + tid;
    int v = (gid < N_NODES) ? g_deg[gid] : 0;
    if (gid < N_NODES) g_dinv[gid] = rsqrtf((float)(v + 1));
    sh[tid] = v;
    __syncthreads();
#pragma unroll
    for (int off = 1; off < SCAN_B; off <<= 1) {
        int t = (tid >= off) ? sh[tid - off] : 0;
        __syncthreads();
        sh[tid] += t;
        __syncthreads();
    }
    if (gid < N_NODES) g_off[gid] = sh[tid] - v;
    if (tid == SCAN_B - 1) g_bsum[blockIdx.x] = sh[tid];
}

__global__ void k_scan2() {
    __shared__ int sh[128];
    int tid = threadIdx.x;
    int v = (tid < N_SCANBLK) ? g_bsum[tid] : 0;
    sh[tid] = v;
    __syncthreads();
#pragma unroll
    for (int off = 1; off < 128; off <<= 1) {
        int t = (tid >= off) ? sh[tid - off] : 0;
        __syncthreads();
        sh[tid] += t;
        __syncthreads();
    }
    if (tid < N_SCANBLK) g_bpre[tid] = sh[tid] - v;
}

__global__ void k_scan3() {
    int gid = blockIdx.x * SCAN_B + threadIdx.x;
    if (gid < N_NODES) {
        int o = g_off[gid] + g_bpre[blockIdx.x];
        g_off[gid] = o;
        g_cur[gid] = o;
    }
    if (gid == 0) g_off[N_NODES] = N_EDGES;
}

// ---------------- CSR fill ----------------
__global__ void k_fill(const int* __restrict__ src, const int* __restrict__ dst) {
    int i = blockIdx.x * blockDim.x + threadIdx.x;
    if (i < N_EDGES) {
        int pos = atomicAdd(&g_cur[dst[i]], 1);
        g_csr[pos] = src[i];
    }
}

#define MMA16816(D, A, B)                                                      \
    asm volatile(                                                              \
        "mma.sync.aligned.m16n8k16.row.col.f32.f16.f16.f32 "                   \
        "{%0,%1,%2,%3}, {%4,%5,%6,%7}, {%8,%9}, {%0,%1,%2,%3};"                \
        : "+f"((D)[0]), "+f"((D)[1]), "+f"((D)[2]), "+f"((D)[3])               \
        : "r"((A)[0]), "r"((A)[1]), "r"((A)[2]), "r"((A)[3]),                  \
          "r"((B)[0]), "r"((B)[1]))

// ---------------- weight convert (run once per call, tiny) ----------------
__global__ void k_convW1(const float* __restrict__ W) {
    int idx = blockIdx.x * blockDim.x + threadIdx.x;   // over F1*F0P
    if (idx >= F1 * F0P) return;
    int n = idx / F0P, k = idx % F0P;
    g_W1T[idx] = __float2half_rn((k < F0) ? W[(size_t)k * F1 + n] : 0.f);
}

__global__ void k_convW2(const float* __restrict__ W) {
    int idx = blockIdx.x * blockDim.x + threadIdx.x;   // over F2*F1
    if (idx >= F2 * F1) return;
    int n = idx / F1, k = idx % F1;
    g_W2T[idx] = __float2half_rn(W[(size_t)k * F2 + n]);
}

// ---------------- GEMM 1 (single fp16 HMMA, double-buffered pipeline) -------
// y1h = half(dinv*(x@W1)); dinv computed in-epilogue from g_deg.
// BM=128, BN=128, BK=16; 8 warps 4(M)x2(N); warp tile 32x64.
__device__ __forceinline__ void g1_loadA(const float* __restrict__ x, int row0,
                                         int k0, int tid, float* f) {
    int r = tid >> 1;
    int c8 = (tid & 1) * 8;
    int grow = row0 + r;
    if (grow < N_NODES) {
        if (k0 + c8 + 8 <= F0) {
            float4 v0 = *(const float4*)&x[(size_t)grow * F0 + k0 + c8];
            float4 v1 = *(const float4*)&x[(size_t)grow * F0 + k0 + c8 + 4];
            f[0]=v0.x; f[1]=v0.y; f[2]=v0.z; f[3]=v0.w;
            f[4]=v1.x; f[5]=v1.y; f[6]=v1.z; f[7]=v1.w;
        } else {
#pragma unroll
            for (int i = 0; i < 8; i++) {
                int kk = k0 + c8 + i;
                f[i] = (kk < F0) ? x[(size_t)grow * F0 + kk] : 0.f;
            }
        }
    } else {
#pragma unroll
        for (int i = 0; i < 8; i++) f[i] = 0.f;
    }
}

__device__ __forceinline__ void g1_loadB(const unsigned* __restrict__ WT,
                                         int k0, int tid, unsigned* vb) {
#pragma unroll
    for (int i = 0; i < 4; i++) {
        int idx = tid + i * 256;          // 0..1023
        int n = idx >> 3, w = idx & 7;
        vb[i] = WT[n * (F0P / 2) + (k0 >> 1) + w];
    }
}

__global__ __launch_bounds__(256) void k_gemm1(const float* __restrict__ x) {
    __shared__ __half Ah[2][128][18];
    __shared__ __half Bh[2][128][18];

    const int tid  = threadIdx.x;
    const int warp = tid >> 5, lane = tid & 31;
    const int wm = warp >> 1, wn = warp & 1;
    const int gr = lane >> 2, ct = lane & 3;
    const int row0 = blockIdx.x * 128;

    float d[2][8][4];
#pragma unroll
    for (int mt = 0; mt < 2; mt++)
#pragma unroll
        for (int nt = 0; nt < 8; nt++)
#pragma unroll
            for (int j = 0; j < 4; j++) d[mt][nt][j] = 0.f;

    const unsigned* WT = (const unsigned*)g_W1T;   // [128][152] u32

    const int ar_ = tid >> 1;
    const int ac8 = (tid & 1) * 8;

    float    va[8];
    unsigned vb[4];

    // prologue: stage tile 0 into buffer 0
    g1_loadA(x, row0, 0, tid, va);
    g1_loadB(WT, 0, tid, vb);
    {
#pragma unroll
        for (int i = 0; i < 4; i++)
            *(__half2*)&Ah[0][ar_][ac8 + 2 * i] =
                __floats2half2_rn(va[2 * i], va[2 * i + 1]);
        unsigned* dh = (unsigned*)Bh[0];
#pragma unroll
        for (int i = 0; i < 4; i++) {
            int idx = tid + i * 256;
            int n = idx >> 3, w = idx & 7;
            dh[n * 9 + w] = vb[i];
        }
    }
    __syncthreads();

    for (int kt = 0; kt < NT1; kt++) {
        int buf = kt & 1;
        // ---- prefetch next tile's gmem into regs (overlaps MMAs below) ----
        if (kt + 1 < NT1) {
            g1_loadA(x, row0, (kt + 1) * 16, tid, va);
            g1_loadB(WT, (kt + 1) * 16, tid, vb);
        }

        // ---- fragments + MMAs on current buffer ----
        unsigned bhf[8][2];
#pragma unroll
        for (int nt = 0; nt < 8; nt++) {
            int nn = wn * 64 + nt * 8 + gr;
            bhf[nt][0] = *(const unsigned*)&Bh[buf][nn][2 * ct];
            bhf[nt][1] = *(const unsigned*)&Bh[buf][nn][2 * ct + 8];
        }
#pragma unroll
        for (int mt = 0; mt < 2; mt++) {
            int ar = wm * 32 + mt * 16 + gr;
            unsigned ah[4];
            ah[0] = *(const unsigned*)&Ah[buf][ar][2 * ct];
            ah[1] = *(const unsigned*)&Ah[buf][ar + 8][2 * ct];
            ah[2] = *(const unsigned*)&Ah[buf][ar][2 * ct + 8];
            ah[3] = *(const unsigned*)&Ah[buf][ar + 8][2 * ct + 8];
#pragma unroll
            for (int nt = 0; nt < 8; nt++)
                MMA16816(d[mt][nt], ah, bhf[nt]);
        }

        // ---- store next tile into the alternate buffer ----
        if (kt + 1 < NT1) {
            int nbuf = buf ^ 1;
#pragma unroll
            for (int i = 0; i < 4; i++)
                *(__half2*)&Ah[nbuf][ar_][ac8 + 2 * i] =
                    __floats2half2_rn(va[2 * i], va[2 * i + 1]);
            unsigned* dh = (unsigned*)Bh[nbuf];
#pragma unroll
            for (int i = 0; i < 4; i++) {
                int idx = tid + i * 256;
                int n = idx >> 3, w = idx & 7;
                dh[n * 9 + w] = vb[i];
            }
            __syncthreads();
        }
    }

    // ---- epilogue: scale by rsqrt(deg+1), store fp16 ----
#pragma unroll
    for (int mt = 0; mt < 2; mt++) {
        int r1 = row0 + wm * 32 + mt * 16 + gr;
        int r2 = r1 + 8;
        float s1 = (r1 < N_NODES) ? rsqrtf((float)(g_deg[r1] + 1)) : 0.f;
        float s2 = (r2 < N_NODES) ? rsqrtf((float)(g_deg[r2] + 1)) : 0.f;
#pragma unroll
        for (int nt = 0; nt < 8; nt++) {
            int c = wn * 64 + nt * 8 + 2 * ct;
            if (r1 < N_NODES)
                *(__half2*)&g_y1h[(size_t)r1 * F1 + c] =
                    __floats2half2_rn(d[mt][nt][0] * s1, d[mt][nt][1] * s1);
            if (r2 < N_NODES)
                *(__half2*)&g_y1h[(size_t)r2 * F1 + c] =
                    __floats2half2_rn(d[mt][nt][2] * s2, d[mt][nt][3] * s2);
        }
    }
}

// ---------------- agg 1: h = relu(dinv[d]*(y1[d] + sum y1[src]) + b1) --------
__global__ void k_agg1(const float* __restrict__ b) {
    int d = blockIdx.x * 8 + (threadIdx.x >> 5);
    if (d >= N_NODES) return;
    int lane = threadIdx.x & 31;
    const float2* Y = (const float2*)g_y1h;   // 32 float2 per row

    float ax[4] = {0.f, 0.f, 0.f, 0.f};
    {
        float2 r = Y[(size_t)d * 32 + lane];  // self loop
        float2 f0 = __half22float2(*(__half2*)&r.x);
        float2 f1 = __half22float2(*(__half2*)&r.y);
        ax[0] = f0.x; ax[1] = f0.y; ax[2] = f1.x; ax[3] = f1.y;
    }
    float ay[4] = {0.f, 0.f, 0.f, 0.f};
    float az[4] = {0.f, 0.f, 0.f, 0.f};
    float aw[4] = {0.f, 0.f, 0.f, 0.f};

    int j = g_off[d], end = g_off[d + 1];
    for (; j + 4 <= end; j += 4) {
        int s0 = g_csr[j], s1 = g_csr[j + 1], s2 = g_csr[j + 2], s3 = g_csr[j + 3];
        float2 r0 = Y[(size_t)s0 * 32 + lane];
        float2 r1 = Y[(size_t)s1 * 32 + lane];
        float2 r2 = Y[(size_t)s2 * 32 + lane];
        float2 r3 = Y[(size_t)s3 * 32 + lane];
        float2 f;
        f = __half22float2(*(__half2*)&r0.x); ax[0] += f.x; ax[1] += f.y;
        f = __half22float2(*(__half2*)&r0.y); ax[2] += f.x; ax[3] += f.y;
        f = __half22float2(*(__half2*)&r1.x); ay[0] += f.x; ay[1] += f.y;
        f = __half22float2(*(__half2*)&r1.y); ay[2] += f.x; ay[3] += f.y;
        f = __half22float2(*(__half2*)&r2.x); az[0] += f.x; az[1] += f.y;
        f = __half22float2(*(__half2*)&r2.y); az[2] += f.x; az[3] += f.y;
        f = __half22float2(*(__half2*)&r3.x); aw[0] += f.x; aw[1] += f.y;
        f = __half22float2(*(__half2*)&r3.y); aw[2] += f.x; aw[3] += f.y;
    }
    for (; j < end; j++) {
        float2 r = Y[(size_t)g_csr[j] * 32 + lane];
        float2 f;
        f = __half22float2(*(__half2*)&r.x); ax[0] += f.x; ax[1] += f.y;
        f = __half22float2(*(__half2*)&r.y); ax[2] += f.x; ax[3] += f.y;
    }
#pragma unroll
    for (int i = 0; i < 4; i++) ax[i] += ay[i] + az[i] + aw[i];

    float s = g_dinv[d];
    float4 bb = ((const float4*)b)[lane];
    float o[4];
    o[0] = fmaxf(fmaf(ax[0], s, bb.x), 0.f);
    o[1] = fmaxf(fmaf(ax[1], s, bb.y), 0.f);
    o[2] = fmaxf(fmaf(ax[2], s, bb.z), 0.f);
    o[3] = fmaxf(fmaf(ax[3], s, bb.w), 0.f);
    __half2 p0 = __floats2half2_rn(o[0], o[1]);
    __half2 p1 = __floats2half2_rn(o[2], o[3]);
    float2 pk;
    pk.x = __uint_as_float(*(unsigned*)&p0);
    pk.y = __uint_as_float(*(unsigned*)&p1);
    *(float2*)&g_hh[(size_t)d * F1 + lane * 4] = pk;
}

// ---------------- GEMM 2 (single fp16 HMMA): y2h = half(dinv*(h@W2)) --------
// BM=128, BN=64, BK=16; 8 warps 4(M)x2(N); warp tile 32x32.
__global__ __launch_bounds__(256) void k_gemm2() {
    __shared__ __half Ah[128][18];
    __shared__ __half Bh[64][18];

    const int tid  = threadIdx.x;
    const int warp = tid >> 5, lane = tid & 31;
    const int wm = warp >> 1, wn = warp & 1;
    const int gr = lane >> 2, ct = lane & 3;
    const int row0 = blockIdx.x * 128;

    float d[2][4][4];
#pragma unroll
    for (int mt = 0; mt < 2; mt++)
#pragma unroll
        for (int nt = 0; nt < 4; nt++)
#pragma unroll
            for (int j = 0; j < 4; j++) d[mt][nt][j] = 0.f;

    const unsigned* HH = (const unsigned*)g_hh;      // [node][64] u32
    const unsigned* WT = (const unsigned*)g_W2T;     // [64][64] u32

    for (int kt = 0; kt < F1 / 16; kt++) {
        int k0 = kt * 16;
        // ---- A tile 128x16: direct u32 copies (already fp16) ----
        {
            int r = tid >> 1;
            int w0 = (tid & 1) * 4;
            int grow = row0 + r;
            unsigned* dh = (unsigned*)Ah;
            if (grow < N_NODES) {
                size_t src = (size_t)grow * 64 + (k0 >> 1) + w0;
#pragma unroll
                for (int i = 0; i < 4; i++)
                    dh[r * 9 + w0 + i] = HH[src + i];
            } else {
#pragma unroll
                for (int i = 0; i < 4; i++)
                    dh[r * 9 + w0 + i] = 0u;
            }
        }
        // ---- B tile: 64 rows x 8 u32 ----
        {
            unsigned* dh = (unsigned*)Bh;
#pragma unroll
            for (int i = 0; i < 2; i++) {
                int idx = tid + i * 256;          // 0..511
                int n = idx >> 3, w = idx & 7;
                dh[n * 9 + w] = WT[n * (F1 / 2) + (k0 >> 1) + w];
            }
        }
        __syncthreads();

        unsigned bh[4][2];
#pragma unroll
        for (int nt = 0; nt < 4; nt++) {
            int nn = wn * 32 + nt * 8 + gr;
            bh[nt][0] = *(const unsigned*)&Bh[nn][2 * ct];
            bh[nt][1] = *(const unsigned*)&Bh[nn][2 * ct + 8];
        }
#pragma unroll
        for (int mt = 0; mt < 2; mt++) {
            int ar = wm * 32 + mt * 16 + gr;
            unsigned ah[4];
            ah[0] = *(const unsigned*)&Ah[ar][2 * ct];
            ah[1] = *(const unsigned*)&Ah[ar + 8][2 * ct];
            ah[2] = *(const unsigned*)&Ah[ar][2 * ct + 8];
            ah[3] = *(const unsigned*)&Ah[ar + 8][2 * ct + 8];
#pragma unroll
            for (int nt = 0; nt < 4; nt++)
                MMA16816(d[mt][nt], ah, bh[nt]);
        }
        __syncthreads();
    }

#pragma unroll
    for (int mt = 0; mt < 2; mt++) {
        int r1 = row0 + wm * 32 + mt * 16 + gr;
        int r2 = r1 + 8;
        float s1 = (r1 < N_NODES) ? g_dinv[r1] : 0.f;
        float s2 = (r2 < N_NODES) ? g_dinv[r2] : 0.f;
#pragma unroll
        for (int nt = 0; nt < 4; nt++) {
            int c = wn * 32 + nt * 8 + 2 * ct;
            if (r1 < N_NODES)
                *(__half2*)&g_y2h[(size_t)r1 * F2 + c] =
                    __floats2half2_rn(d[mt][nt][0] * s1, d[mt][nt][1] * s1);
            if (r2 < N_NODES)
                *(__half2*)&g_y2h[(size_t)r2 * F2 + c] =
                    __floats2half2_rn(d[mt][nt][2] * s2, d[mt][nt][3] * s2);
        }
    }
}

// ---------------- agg 2: out = dinv[d]*(y2[d] + sum y2[src]) + b2 ----------------
__global__ void k_agg2(const float* __restrict__ b, float* __restrict__ out) {
    int d = blockIdx.x * 8 + (threadIdx.x >> 5);
    if (d >= N_NODES) return;
    int lane = threadIdx.x & 31;
    const __half2* Y = (const __half2*)g_y2h;   // 32 half2 per row

    float2 a0 = __half22float2(Y[(size_t)d * 32 + lane]);  // self loop
    float2 a1 = make_float2(0.f, 0.f);
    float2 a2 = make_float2(0.f, 0.f);
    float2 a3 = make_float2(0.f, 0.f);

    int j = g_off[d], end = g_off[d + 1];
    for (; j + 4 <= end; j += 4) {
        int s0 = g_csr[j], s1 = g_csr[j + 1], s2 = g_csr[j + 2], s3 = g_csr[j + 3];
        float2 v0 = __half22float2(Y[(size_t)s0 * 32 + lane]);
        float2 v1 = __half22float2(Y[(size_t)s1 * 32 + lane]);
        float2 v2 = __half22float2(Y[(size_t)s2 * 32 + lane]);
        float2 v3 = __half22float2(Y[(size_t)s3 * 32 + lane]);
        a0.x += v0.x; a0.y += v0.y;
        a1.x += v1.x; a1.y += v1.y;
        a2.x += v2.x; a2.y += v2.y;
        a3.x += v3.x; a3.y += v3.y;
    }
    for (; j < end; j++) {
        float2 v = __half22float2(Y[(size_t)g_csr[j] * 32 + lane]);
        a0.x += v.x; a0.y += v.y;
    }
    float2 acc = make_float2(a0.x + a1.x + a2.x + a3.x,
                             a0.y + a1.y + a2.y + a3.y);
    float s = g_dinv[d];
    float2 bb = ((const float2*)b)[lane];
    acc.x = fmaf(acc.x, s, bb.x);
    acc.y = fmaf(acc.y, s, bb.y);
    ((float2*)out)[(size_t)d * 32 + lane] = acc;
}

extern "C" void kernel_launch(void* const* d_in, const int* in_sizes, int n_in,
                              void* d_out, int out_size) {
    const float* x   = (const float*)d_in[0];
    const int*   ei  = (const int*)d_in[1];
    const float* W1  = (const float*)d_in[2];
    const float* b1  = (const float*)d_in[3];
    const float* W2  = (const float*)d_in[4];
    const float* b2  = (const float*)d_in[5];
    float*       out = (float*)d_out;

    const int* src = ei;
    const int* dst = ei + N_EDGES;

    // ---- branch C: weight conversion (independent of everything else) ----
    cudaEventRecord(ev_root, 0);
    cudaStreamWaitEvent(s_conv, ev_root, 0);
    k_convW1<<<(F1 * F0P + 255) / 256, 256, 0, s_conv>>>(W1);
    k_convW2<<<(F2 * F1 + 255) / 256, 256, 0, s_conv>>>(W2);
    cudaEventRecord(ev_conv, s_conv);

    // ---- main stream: degree ----
    k_zero_deg<<<(N_NODES + 255) / 256, 256>>>();
    k_count<<<(N_EDGES + 255) / 256, 256>>>(dst);

    // ---- branch B: CSR build (scan + fill), concurrent with gemm1 ----
    cudaEventRecord(ev_cnt, 0);
    cudaStreamWaitEvent(s_csr, ev_cnt, 0);
    k_scan1<<<N_SCANBLK, SCAN_B, 0, s_csr>>>();   // also writes g_dinv
    k_scan2<<<1, 128, 0, s_csr>>>();
    k_scan3<<<N_SCANBLK, SCAN_B, 0, s_csr>>>();
    k_fill<<<(N_EDGES + 255) / 256, 256, 0, s_csr>>>(src, dst);
    cudaEventRecord(ev_csr, s_csr);

    // ---- main stream: gemm1 (waits on weights; dinv computed in-epilogue) ----
    cudaStreamWaitEvent(0, ev_conv, 0);
    k_gemm1<<<(N_NODES + 127) / 128, 256>>>(x);

    // ---- join CSR branch, then aggregate + layer 2 ----
    cudaStreamWaitEvent(0, ev_csr, 0);
    k_agg1<<<(N_NODES + 7) / 8, 256>>>(b1);
    k_gemm2<<<(N_NODES + 127) / 128, 256>>>();
    k_agg2<<<(N_NODES + 7) / 8, 256>>>(b2, out);
}

// round 14
// speedup vs baseline: 1.4113x; 1.4113x over previous
#include <cuda_runtime.h>
#include <cuda_fp16.h>

#define N_NODES 100000
#define N_EDGES 3200000
#define F0 300
#define F0P 304            // padded K for GEMM1 (19 * 16)
#define F1 128
#define F2 64

#define SCAN_B 1024
#define N_SCANBLK ((N_NODES + SCAN_B - 1) / SCAN_B)   // 98

// ---- scratch (static device allocations; no cudaMalloc allowed) ----
__device__ int    g_deg[N_NODES];
__device__ int    g_off[N_NODES + 1];
__device__ int    g_cur[N_NODES];
__device__ int    g_csr[N_EDGES];
__device__ int    g_bsum[N_SCANBLK];
__device__ int    g_bpre[N_SCANBLK];
__device__ float  g_dinv[N_NODES];
__device__ __half g_y1h[(size_t)N_NODES * F1];   // fp16 message rows, layer 1
__device__ __half g_hh[(size_t)N_NODES * F1];    // hidden, fp16
__device__ __half g_y2h[(size_t)N_NODES * F2];   // fp16 message rows, layer 2
// pre-converted, pre-transposed weights: [n][k] with k contiguous
__device__ __half g_W1T[F1 * F0P];
__device__ __half g_W2T[F2 * F1];

// ---- streams/events for fork-join inside the captured graph ----
static cudaStream_t s_conv, s_csr;
static cudaEvent_t  ev_root, ev_conv, ev_cnt, ev_csr;
struct _InitStreams {
    _InitStreams() {
        cudaStreamCreateWithFlags(&s_conv, cudaStreamNonBlocking);
        cudaStreamCreateWithFlags(&s_csr, cudaStreamNonBlocking);
        cudaEventCreateWithFlags(&ev_root, cudaEventDisableTiming);
        cudaEventCreateWithFlags(&ev_conv, cudaEventDisableTiming);
        cudaEventCreateWithFlags(&ev_cnt, cudaEventDisableTiming);
        cudaEventCreateWithFlags(&ev_csr, cudaEventDisableTiming);
    }
};
static _InitStreams _g_init_streams;

// ---------------- degree ----------------
__global__ void k_zero_deg() {
    int i = blockIdx.x * blockDim.x + threadIdx.x;
    if (i < N_NODES) g_deg[i] = 0;
}

__global__ void k_count(const int* __restrict__ dst) {
    int i = blockIdx.x * blockDim.x + threadIdx.x;
    if (i < N_EDGES) atomicAdd(&g_deg[dst[i]], 1);
}

// ---------------- scan (3 phases; scan1 also computes dinv) ----------------
__global__ void k_scan1() {
    __shared__ int sh[SCAN_B];
    int tid = threadIdx.x;
    int gid = blockIdx.x * SCAN_B + tid;
    int v = (gid < N_NODES) ? g_deg[gid] : 0;
    if (gid < N_NODES) g_dinv[gid] = rsqrtf((float)(v + 1));
    sh[tid] = v;
    __syncthreads();
#pragma unroll
    for (int off = 1; off < SCAN_B; off <<= 1) {
        int t = (tid >= off) ? sh[tid - off] : 0;
        __syncthreads();
        sh[tid] += t;
        __syncthreads();
    }
    if (gid < N_NODES) g_off[gid] = sh[tid] - v;
    if (tid == SCAN_B - 1) g_bsum[blockIdx.x] = sh[tid];
}

__global__ void k_scan2() {
    __shared__ int sh[128];
    int tid = threadIdx.x;
    int v = (tid < N_SCANBLK) ? g_bsum[tid] : 0;
    sh[tid] = v;
    __syncthreads();
#pragma unroll
    for (int off = 1; off < 128; off <<= 1) {
        int t = (tid >= off) ? sh[tid - off] : 0;
        __syncthreads();
        sh[tid] += t;
        __syncthreads();
    }
    if (tid < N_SCANBLK) g_bpre[tid] = sh[tid] - v;
}

__global__ void k_scan3() {
    int gid = blockIdx.x * SCAN_B + threadIdx.x;
    if (gid < N_NODES) {
        int o = g_off[gid] + g_bpre[blockIdx.x];
        g_off[gid] = o;
        g_cur[gid] = o;
    }
    if (gid == 0) g_off[N_NODES] = N_EDGES;
}

// ---------------- CSR fill ----------------
__global__ void k_fill(const int* __restrict__ src, const int* __restrict__ dst) {
    int i = blockIdx.x * blockDim.x + threadIdx.x;
    if (i < N_EDGES) {
        int pos = atomicAdd(&g_cur[dst[i]], 1);
        g_csr[pos] = src[i];
    }
}

#define MMA16816(D, A, B)                                                      \
    asm volatile(                                                              \
        "mma.sync.aligned.m16n8k16.row.col.f32.f16.f16.f32 "                   \
        "{%0,%1,%2,%3}, {%4,%5,%6,%7}, {%8,%9}, {%0,%1,%2,%3};"                \
        : "+f"((D)[0]), "+f"((D)[1]), "+f"((D)[2]), "+f"((D)[3])               \
        : "r"((A)[0]), "r"((A)[1]), "r"((A)[2]), "r"((A)[3]),                  \
          "r"((B)[0]), "r"((B)[1]))

// ---------------- weight convert (run once per call, tiny) ----------------
__global__ void k_convW1(const float* __restrict__ W) {
    int idx = blockIdx.x * blockDim.x + threadIdx.x;   // over F1*F0P
    if (idx >= F1 * F0P) return;
    int n = idx / F0P, k = idx % F0P;
    g_W1T[idx] = __float2half_rn((k < F0) ? W[(size_t)k * F1 + n] : 0.f);
}

__global__ void k_convW2(const float* __restrict__ W) {
    int idx = blockIdx.x * blockDim.x + threadIdx.x;   // over F2*F1
    if (idx >= F2 * F1) return;
    int n = idx / F1, k = idx % F1;
    g_W2T[idx] = __float2half_rn(W[(size_t)k * F2 + n]);
}

// ---------------- GEMM 1 (single fp16 HMMA): y1h = half(dinv*(x@W1)) --------
// BM=128, BN=128, BK=16; 8 warps 4(M)x2(N); warp tile 32x64.
__global__ __launch_bounds__(256) void k_gemm1(const float* __restrict__ x) {
    __shared__ __half Ah[128][18];
    __shared__ __half Bh[128][18];

    const int tid  = threadIdx.x;
    const int warp = tid >> 5, lane = tid & 31;
    const int wm = warp >> 1, wn = warp & 1;
    const int gr = lane >> 2, ct = lane & 3;
    const int row0 = blockIdx.x * 128;

    float d[2][8][4];
#pragma unroll
    for (int mt = 0; mt < 2; mt++)
#pragma unroll
        for (int nt = 0; nt < 8; nt++)
#pragma unroll
            for (int j = 0; j < 4; j++) d[mt][nt][j] = 0.f;

    const unsigned* WT = (const unsigned*)g_W1T;   // [128][152] u32

    for (int kt = 0; kt < F0P / 16; kt++) {
        int k0 = kt * 16;
        // ---- A tile 128x16 fp32 -> fp16 ----
        {
            int r = tid >> 1;
            int c8 = (tid & 1) * 8;
            int grow = row0 + r;
            float f[8];
            if (grow < N_NODES) {
                if (k0 + c8 + 8 <= F0) {
                    float4 v0 = *(const float4*)&x[(size_t)grow * F0 + k0 + c8];
                    float4 v1 = *(const float4*)&x[(size_t)grow * F0 + k0 + c8 + 4];
                    f[0]=v0.x; f[1]=v0.y; f[2]=v0.z; f[3]=v0.w;
                    f[4]=v1.x; f[5]=v1.y; f[6]=v1.z; f[7]=v1.w;
                } else {
#pragma unroll
                    for (int i = 0; i < 8; i++) {
                        int kk = k0 + c8 + i;
                        f[i] = (kk < F0) ? x[(size_t)grow * F0 + kk] : 0.f;
                    }
                }
            } else {
#pragma unroll
                for (int i = 0; i < 8; i++) f[i] = 0.f;
            }
#pragma unroll
            for (int i = 0; i < 4; i++)
                *(__half2*)&Ah[r][c8 + 2 * i] =
                    __floats2half2_rn(f[2 * i], f[2 * i + 1]);
        }
        // ---- B tile: copy 128 rows x 8 u32 from pre-converted transposed W ----
        {
            unsigned* dh = (unsigned*)Bh;
#pragma unroll
            for (int i = 0; i < 4; i++) {
                int idx = tid + i * 256;          // 0..1023
                int n = idx >> 3, w = idx & 7;
                dh[n * 9 + w] = WT[n * (F0P / 2) + (k0 >> 1) + w];
            }
        }
        __syncthreads();

        // ---- hoisted B fragments ----
        unsigned bh[8][2];
#pragma unroll
        for (int nt = 0; nt < 8; nt++) {
            int nn = wn * 64 + nt * 8 + gr;
            bh[nt][0] = *(const unsigned*)&Bh[nn][2 * ct];
            bh[nt][1] = *(const unsigned*)&Bh[nn][2 * ct + 8];
        }
#pragma unroll
        for (int mt = 0; mt < 2; mt++) {
            int ar = wm * 32 + mt * 16 + gr;
            unsigned ah[4];
            ah[0] = *(const unsigned*)&Ah[ar][2 * ct];
            ah[1] = *(const unsigned*)&Ah[ar + 8][2 * ct];
            ah[2] = *(const unsigned*)&Ah[ar][2 * ct + 8];
            ah[3] = *(const unsigned*)&Ah[ar + 8][2 * ct + 8];
#pragma unroll
            for (int nt = 0; nt < 8; nt++)
                MMA16816(d[mt][nt], ah, bh[nt]);
        }
        __syncthreads();
    }

    // ---- epilogue: scale by rsqrt(deg+1) read from g_deg, store fp16 ----
#pragma unroll
    for (int mt = 0; mt < 2; mt++) {
        int r1 = row0 + wm * 32 + mt * 16 + gr;
        int r2 = r1 + 8;
        float s1 = (r1 < N_NODES) ? rsqrtf((float)(g_deg[r1] + 1)) : 0.f;
        float s2 = (r2 < N_NODES) ? rsqrtf((float)(g_deg[r2] + 1)) : 0.f;
#pragma unroll
        for (int nt = 0; nt < 8; nt++) {
            int c = wn * 64 + nt * 8 + 2 * ct;
            if (r1 < N_NODES)
                *(__half2*)&g_y1h[(size_t)r1 * F1 + c] =
                    __floats2half2_rn(d[mt][nt][0] * s1, d[mt][nt][1] * s1);
            if (r2 < N_NODES)
                *(__half2*)&g_y1h[(size_t)r2 * F1 + c] =
                    __floats2half2_rn(d[mt][nt][2] * s2, d[mt][nt][3] * s2);
        }
    }
}

// ---------------- agg 1: h = relu(dinv[d]*(y1[d] + sum y1[src]) + b1) --------
__global__ void k_agg1(const float* __restrict__ b) {
    int d = blockIdx.x * 8 + (threadIdx.x >> 5);
    if (d >= N_NODES) return;
    int lane = threadIdx.x & 31;
    const float2* Y = (const float2*)g_y1h;   // 32 float2 per row

    float ax[4] = {0.f, 0.f, 0.f, 0.f};
    {
        float2 r = Y[(size_t)d * 32 + lane];  // self loop
        float2 f0 = __half22float2(*(__half2*)&r.x);
        float2 f1 = __half22float2(*(__half2*)&r.y);
        ax[0] = f0.x; ax[1] = f0.y; ax[2] = f1.x; ax[3] = f1.y;
    }
    float ay[4] = {0.f, 0.f, 0.f, 0.f};
    float az[4] = {0.f, 0.f, 0.f, 0.f};
    float aw[4] = {0.f, 0.f, 0.f, 0.f};

    int j = g_off[d], end = g_off[d + 1];
    for (; j + 4 <= end; j += 4) {
        int s0 = g_csr[j], s1 = g_csr[j + 1], s2 = g_csr[j + 2], s3 = g_csr[j + 3];
        float2 r0 = Y[(size_t)s0 * 32 + lane];
        float2 r1 = Y[(size_t)s1 * 32 + lane];
        float2 r2 = Y[(size_t)s2 * 32 + lane];
        float2 r3 = Y[(size_t)s3 * 32 + lane];
        float2 f;
        f = __half22float2(*(__half2*)&r0.x); ax[0] += f.x; ax[1] += f.y;
        f = __half22float2(*(__half2*)&r0.y); ax[2] += f.x; ax[3] += f.y;
        f = __half22float2(*(__half2*)&r1.x); ay[0] += f.x; ay[1] += f.y;
        f = __half22float2(*(__half2*)&r1.y); ay[2] += f.x; ay[3] += f.y;
        f = __half22float2(*(__half2*)&r2.x); az[0] += f.x; az[1] += f.y;
        f = __half22float2(*(__half2*)&r2.y); az[2] += f.x; az[3] += f.y;
        f = __half22float2(*(__half2*)&r3.x); aw[0] += f.x; aw[1] += f.y;
        f = __half22float2(*(__half2*)&r3.y); aw[2] += f.x; aw[3] += f.y;
    }
    for (; j < end; j++) {
        float2 r = Y[(size_t)g_csr[j] * 32 + lane];
        float2 f;
        f = __half22float2(*(__half2*)&r.x); ax[0] += f.x; ax[1] += f.y;
        f = __half22float2(*(__half2*)&r.y); ax[2] += f.x; ax[3] += f.y;
    }
#pragma unroll
    for (int i = 0; i < 4; i++) ax[i] += ay[i] + az[i] + aw[i];

    float s = g_dinv[d];
    float4 bb = ((const float4*)b)[lane];
    float o[4];
    o[0] = fmaxf(fmaf(ax[0], s, bb.x), 0.f);
    o[1] = fmaxf(fmaf(ax[1], s, bb.y), 0.f);
    o[2] = fmaxf(fmaf(ax[2], s, bb.z), 0.f);
    o[3] = fmaxf(fmaf(ax[3], s, bb.w), 0.f);
    __half2 p0 = __floats2half2_rn(o[0], o[1]);
    __half2 p1 = __floats2half2_rn(o[2], o[3]);
    float2 pk;
    pk.x = __uint_as_float(*(unsigned*)&p0);
    pk.y = __uint_as_float(*(unsigned*)&p1);
    *(float2*)&g_hh[(size_t)d * F1 + lane * 4] = pk;
}

// ---------------- GEMM 2 (single fp16 HMMA): y2h = half(dinv*(h@W2)) --------
// BM=128, BN=64, BK=16; 8 warps 4(M)x2(N); warp tile 32x32.
__global__ __launch_bounds__(256) void k_gemm2() {
    __shared__ __half Ah[128][18];
    __shared__ __half Bh[64][18];

    const int tid  = threadIdx.x;
    const int warp = tid >> 5, lane = tid & 31;
    const int wm = warp >> 1, wn = warp & 1;
    const int gr = lane >> 2, ct = lane & 3;
    const int row0 = blockIdx.x * 128;

    float d[2][4][4];
#pragma unroll
    for (int mt = 0; mt < 2; mt++)
#pragma unroll
        for (int nt = 0; nt < 4; nt++)
#pragma unroll
            for (int j = 0; j < 4; j++) d[mt][nt][j] = 0.f;

    const unsigned* HH = (const unsigned*)g_hh;      // [node][64] u32
    const unsigned* WT = (const unsigned*)g_W2T;     // [64][64] u32

    for (int kt = 0; kt < F1 / 16; kt++) {
        int k0 = kt * 16;
        // ---- A tile 128x16: direct u32 copies (already fp16) ----
        {
            int r = tid >> 1;
            int w0 = (tid & 1) * 4;
            int grow = row0 + r;
            unsigned* dh = (unsigned*)Ah;
            if (grow < N_NODES) {
                size_t src = (size_t)grow * 64 + (k0 >> 1) + w0;
#pragma unroll
                for (int i = 0; i < 4; i++)
                    dh[r * 9 + w0 + i] = HH[src + i];
            } else {
#pragma unroll
                for (int i = 0; i < 4; i++)
                    dh[r * 9 + w0 + i] = 0u;
            }
        }
        // ---- B tile: 64 rows x 8 u32 ----
        {
            unsigned* dh = (unsigned*)Bh;
#pragma unroll
            for (int i = 0; i < 2; i++) {
                int idx = tid + i * 256;          // 0..511
                int n = idx >> 3, w = idx & 7;
                dh[n * 9 + w] = WT[n * (F1 / 2) + (k0 >> 1) + w];
            }
        }
        __syncthreads();

        unsigned bh[4][2];
#pragma unroll
        for (int nt = 0; nt < 4; nt++) {
            int nn = wn * 32 + nt * 8 + gr;
            bh[nt][0] = *(const unsigned*)&Bh[nn][2 * ct];
            bh[nt][1] = *(const unsigned*)&Bh[nn][2 * ct + 8];
        }
#pragma unroll
        for (int mt = 0; mt < 2; mt++) {
            int ar = wm * 32 + mt * 16 + gr;
            unsigned ah[4];
            ah[0] = *(const unsigned*)&Ah[ar][2 * ct];
            ah[1] = *(const unsigned*)&Ah[ar + 8][2 * ct];
            ah[2] = *(const unsigned*)&Ah[ar][2 * ct + 8];
            ah[3] = *(const unsigned*)&Ah[ar + 8][2 * ct + 8];
#pragma unroll
            for (int nt = 0; nt < 4; nt++)
                MMA16816(d[mt][nt], ah, bh[nt]);
        }
        __syncthreads();
    }

#pragma unroll
    for (int mt = 0; mt < 2; mt++) {
        int r1 = row0 + wm * 32 + mt * 16 + gr;
        int r2 = r1 + 8;
        float s1 = (r1 < N_NODES) ? g_dinv[r1] : 0.f;
        float s2 = (r2 < N_NODES) ? g_dinv[r2] : 0.f;
#pragma unroll
        for (int nt = 0; nt < 4; nt++) {
            int c = wn * 32 + nt * 8 + 2 * ct;
            if (r1 < N_NODES)
                *(__half2*)&g_y2h[(size_t)r1 * F2 + c] =
                    __floats2half2_rn(d[mt][nt][0] * s1, d[mt][nt][1] * s1);
            if (r2 < N_NODES)
                *(__half2*)&g_y2h[(size_t)r2 * F2 + c] =
                    __floats2half2_rn(d[mt][nt][2] * s2, d[mt][nt][3] * s2);
        }
    }
}

// ---------------- agg 2: out = dinv[d]*(y2[d] + sum y2[src]) + b2 ----------------
__global__ void k_agg2(const float* __restrict__ b, float* __restrict__ out) {
    int d = blockIdx.x * 8 + (threadIdx.x >> 5);
    if (d >= N_NODES) return;
    int lane = threadIdx.x & 31;
    const __half2* Y = (const __half2*)g_y2h;   // 32 half2 per row

    float2 a0 = __half22float2(Y[(size_t)d * 32 + lane]);  // self loop
    float2 a1 = make_float2(0.f, 0.f);
    float2 a2 = make_float2(0.f, 0.f);
    float2 a3 = make_float2(0.f, 0.f);

    int j = g_off[d], end = g_off[d + 1];
    for (; j + 4 <= end; j += 4) {
        int s0 = g_csr[j], s1 = g_csr[j + 1], s2 = g_csr[j + 2], s3 = g_csr[j + 3];
        float2 v0 = __half22float2(Y[(size_t)s0 * 32 + lane]);
        float2 v1 = __half22float2(Y[(size_t)s1 * 32 + lane]);
        float2 v2 = __half22float2(Y[(size_t)s2 * 32 + lane]);
        float2 v3 = __half22float2(Y[(size_t)s3 * 32 + lane]);
        a0.x += v0.x; a0.y += v0.y;
        a1.x += v1.x; a1.y += v1.y;
        a2.x += v2.x; a2.y += v2.y;
        a3.x += v3.x; a3.y += v3.y;
    }
    for (; j < end; j++) {
        float2 v = __half22float2(Y[(size_t)g_csr[j] * 32 + lane]);
        a0.x += v.x; a0.y += v.y;
    }
    float2 acc = make_float2(a0.x + a1.x + a2.x + a3.x,
                             a0.y + a1.y + a2.y + a3.y);
    float s = g_dinv[d];
    float2 bb = ((const float2*)b)[lane];
    acc.x = fmaf(acc.x, s, bb.x);
    acc.y = fmaf(acc.y, s, bb.y);
    ((float2*)out)[(size_t)d * 32 + lane] = acc;
}

extern "C" void kernel_launch(void* const* d_in, const int* in_sizes, int n_in,
                              void* d_out, int out_size) {
    const float* x   = (const float*)d_in[0];
    const int*   ei  = (const int*)d_in[1];
    const float* W1  = (const float*)d_in[2];
    const float* b1  = (const float*)d_in[3];
    const float* W2  = (const float*)d_in[4];
    const float* b2  = (const float*)d_in[5];
    float*       out = (float*)d_out;

    const int* src = ei;
    const int* dst = ei + N_EDGES;

    // ---- branch C: weight conversion (independent of everything else) ----
    cudaEventRecord(ev_root, 0);
    cudaStreamWaitEvent(s_conv, ev_root, 0);
    k_convW1<<<(F1 * F0P + 255) / 256, 256, 0, s_conv>>>(W1);
    k_convW2<<<(F2 * F1 + 255) / 256, 256, 0, s_conv>>>(W2);
    cudaEventRecord(ev_conv, s_conv);

    // ---- main stream: degree ----
    k_zero_deg<<<(N_NODES + 255) / 256, 256>>>();
    k_count<<<(N_EDGES + 255) / 256, 256>>>(dst);

    // ---- branch B: CSR build (scan + fill), concurrent with gemm1 ----
    cudaEventRecord(ev_cnt, 0);
    cudaStreamWaitEvent(s_csr, ev_cnt, 0);
    k_scan1<<<N_SCANBLK, SCAN_B, 0, s_csr>>>();   // also writes g_dinv
    k_scan2<<<1, 128, 0, s_csr>>>();
    k_scan3<<<N_SCANBLK, SCAN_B, 0, s_csr>>>();
    k_fill<<<(N_EDGES + 255) / 256, 256, 0, s_csr>>>(src, dst);
    cudaEventRecord(ev_csr, s_csr);

    // ---- main stream: gemm1 (waits on weights; dinv from g_deg in-epilogue) ----
    cudaStreamWaitEvent(0, ev_conv, 0);
    k_gemm1<<<(N_NODES + 127) / 128, 256>>>(x);

    // ---- join CSR branch, then aggregate + layer 2 ----
    cudaStreamWaitEvent(0, ev_csr, 0);
    k_agg1<<<(N_NODES + 7) / 8, 256>>>(b1);
    k_gemm2<<<(N_NODES + 127) / 128, 256>>>();
    k_agg2<<<(N_NODES + 7) / 8, 256>>>(b2, out);
}

// round 15
// speedup vs baseline: 1.4343x; 1.0163x over previous
#include <cuda_runtime.h>
#include <cuda_fp16.h>

#define N_NODES 100000
#define N_EDGES 3200000
#define F0 300
#define F0P 304            // padded K for GEMM1 (19 * 16)
#define F1 128
#define F2 64

#define SCAN_B 1024
#define N_SCANBLK ((N_NODES + SCAN_B - 1) / SCAN_B)   // 98

// ---- scratch (static device allocations; no cudaMalloc allowed) ----
__device__ int    g_deg[N_NODES];
__device__ int    g_off[N_NODES + 1];
__device__ int    g_cur[N_NODES];
__device__ int    g_csr[N_EDGES];
__device__ int    g_bsum[N_SCANBLK];
__device__ int    g_bpre[N_SCANBLK];
__device__ float  g_dinv[N_NODES];
__device__ __half g_y1h[(size_t)N_NODES * F1];   // fp16 message rows, layer 1
__device__ __half g_hh[(size_t)N_NODES * F1];    // hidden, fp16
__device__ __half g_y2h[(size_t)N_NODES * F2];   // fp16 message rows, layer 2
// pre-converted, pre-transposed weights: [n][k] with k contiguous
__device__ __half g_W1T[F1 * F0P];
__device__ __half g_W2T[F2 * F1];

// ---- streams/events for fork-join inside the captured graph ----
static cudaStream_t s_conv, s_csr;
static cudaEvent_t  ev_root, ev_conv, ev_cnt, ev_csr;
struct _InitStreams {
    _InitStreams() {
        cudaStreamCreateWithFlags(&s_conv, cudaStreamNonBlocking);
        cudaStreamCreateWithFlags(&s_csr, cudaStreamNonBlocking);
        cudaEventCreateWithFlags(&ev_root, cudaEventDisableTiming);
        cudaEventCreateWithFlags(&ev_conv, cudaEventDisableTiming);
        cudaEventCreateWithFlags(&ev_cnt, cudaEventDisableTiming);
        cudaEventCreateWithFlags(&ev_csr, cudaEventDisableTiming);
    }
};
static _InitStreams _g_init_streams;

// ---------------- degree ----------------
__global__ void k_zero_deg() {
    int i = blockIdx.x * blockDim.x + threadIdx.x;
    if (i < N_NODES) g_deg[i] = 0;
}

__global__ void k_count(const int* __restrict__ dst) {
    int i = blockIdx.x * blockDim.x + threadIdx.x;
    if (i < N_EDGES) atomicAdd(&g_deg[dst[i]], 1);
}

// ---------------- scan (3 phases; scan1 also computes dinv) ----------------
__global__ void k_scan1() {
    __shared__ int sh[SCAN_B];
    int tid = threadIdx.x;
    int gid = blockIdx.x * SCAN_B + tid;
    int v = (gid < N_NODES) ? g_deg[gid] : 0;
    if (gid < N_NODES) g_dinv[gid] = rsqrtf((float)(v + 1));
    sh[tid] = v;
    __syncthreads();
#pragma unroll
    for (int off = 1; off < SCAN_B; off <<= 1) {
        int t = (tid >= off) ? sh[tid - off] : 0;
        __syncthreads();
        sh[tid] += t;
        __syncthreads();
    }
    if (gid < N_NODES) g_off[gid] = sh[tid] - v;
    if (tid == SCAN_B - 1) g_bsum[blockIdx.x] = sh[tid];
}

__global__ void k_scan2() {
    __shared__ int sh[128];
    int tid = threadIdx.x;
    int v = (tid < N_SCANBLK) ? g_bsum[tid] : 0;
    sh[tid] = v;
    __syncthreads();
#pragma unroll
    for (int off = 1; off < 128; off <<= 1) {
        int t = (tid >= off) ? sh[tid - off] : 0;
        __syncthreads();
        sh[tid] += t;
        __syncthreads();
    }
    if (tid < N_SCANBLK) g_bpre[tid] = sh[tid] - v;
}

__global__ void k_scan3() {
    int gid = blockIdx.x * SCAN_B + threadIdx.x;
    if (gid < N_NODES) {
        int o = g_off[gid] + g_bpre[blockIdx.x];
        g_off[gid] = o;
        g_cur[gid] = o;
    }
    if (gid == 0) g_off[N_NODES] = N_EDGES;
}

// ---------------- CSR fill ----------------
__global__ void k_fill(const int* __restrict__ src, const int* __restrict__ dst) {
    int i = blockIdx.x * blockDim.x + threadIdx.x;
    if (i < N_EDGES) {
        int pos = atomicAdd(&g_cur[dst[i]], 1);
        g_csr[pos] = src[i];
    }
}

#define MMA16816(D, A, B)                                                      \
    asm volatile(                                                              \
        "mma.sync.aligned.m16n8k16.row.col.f32.f16.f16.f32 "                   \
        "{%0,%1,%2,%3}, {%4,%5,%6,%7}, {%8,%9}, {%0,%1,%2,%3};"                \
        : "+f"((D)[0]), "+f"((D)[1]), "+f"((D)[2]), "+f"((D)[3])               \
        : "r"((A)[0]), "r"((A)[1]), "r"((A)[2]), "r"((A)[3]),                  \
          "r"((B)[0]), "r"((B)[1]))

// ---------------- weight convert (run once per call, tiny) ----------------
__global__ void k_convW1(const float* __restrict__ W) {
    int idx = blockIdx.x * blockDim.x + threadIdx.x;   // over F1*F0P
    if (idx >= F1 * F0P) return;
    int n = idx / F0P, k = idx % F0P;
    g_W1T[idx] = __float2half_rn((k < F0) ? W[(size_t)k * F1 + n] : 0.f);
}

__global__ void k_convW2(const float* __restrict__ W) {
    int idx = blockIdx.x * blockDim.x + threadIdx.x;   // over F2*F1
    if (idx >= F2 * F1) return;
    int n = idx / F1, k = idx % F1;
    g_W2T[idx] = __float2half_rn(W[(size_t)k * F2 + n]);
}

// ---------------- GEMM 1 (single fp16 HMMA): y1h = half(dinv*(x@W1)) --------
// BM=128, BN=128, BK=16; 8 warps 4(M)x2(N); warp tile 32x64.
__global__ __launch_bounds__(256) void k_gemm1(const float* __restrict__ x) {
    __shared__ __half Ah[128][18];
    __shared__ __half Bh[128][18];

    const int tid  = threadIdx.x;
    const int warp = tid >> 5, lane = tid & 31;
    const int wm = warp >> 1, wn = warp & 1;
    const int gr = lane >> 2, ct = lane & 3;
    const int row0 = blockIdx.x * 128;

    float d[2][8][4];
#pragma unroll
    for (int mt = 0; mt < 2; mt++)
#pragma unroll
        for (int nt = 0; nt < 8; nt++)
#pragma unroll
            for (int j = 0; j < 4; j++) d[mt][nt][j] = 0.f;

    const unsigned* WT = (const unsigned*)g_W1T;   // [128][152] u32

    for (int kt = 0; kt < F0P / 16; kt++) {
        int k0 = kt * 16;
        // ---- A tile 128x16 fp32 -> fp16 ----
        {
            int r = tid >> 1;
            int c8 = (tid & 1) * 8;
            int grow = row0 + r;
            float f[8];
            if (grow < N_NODES) {
                if (k0 + c8 + 8 <= F0) {
                    float4 v0 = *(const float4*)&x[(size_t)grow * F0 + k0 + c8];
                    float4 v1 = *(const float4*)&x[(size_t)grow * F0 + k0 + c8 + 4];
                    f[0]=v0.x; f[1]=v0.y; f[2]=v0.z; f[3]=v0.w;
                    f[4]=v1.x; f[5]=v1.y; f[6]=v1.z; f[7]=v1.w;
                } else {
#pragma unroll
                    for (int i = 0; i < 8; i++) {
                        int kk = k0 + c8 + i;
                        f[i] = (kk < F0) ? x[(size_t)grow * F0 + kk] : 0.f;
                    }
                }
            } else {
#pragma unroll
                for (int i = 0; i < 8; i++) f[i] = 0.f;
            }
#pragma unroll
            for (int i = 0; i < 4; i++)
                *(__half2*)&Ah[r][c8 + 2 * i] =
                    __floats2half2_rn(f[2 * i], f[2 * i + 1]);
        }
        // ---- B tile: copy 128 rows x 8 u32 from pre-converted transposed W ----
        {
            unsigned* dh = (unsigned*)Bh;
#pragma unroll
            for (int i = 0; i < 4; i++) {
                int idx = tid + i * 256;          // 0..1023
                int n = idx >> 3, w = idx & 7;
                dh[n * 9 + w] = WT[n * (F0P / 2) + (k0 >> 1) + w];
            }
        }
        __syncthreads();

        // ---- hoisted B fragments ----
        unsigned bh[8][2];
#pragma unroll
        for (int nt = 0; nt < 8; nt++) {
            int nn = wn * 64 + nt * 8 + gr;
            bh[nt][0] = *(const unsigned*)&Bh[nn][2 * ct];
            bh[nt][1] = *(const unsigned*)&Bh[nn][2 * ct + 8];
        }
#pragma unroll
        for (int mt = 0; mt < 2; mt++) {
            int ar = wm * 32 + mt * 16 + gr;
            unsigned ah[4];
            ah[0] = *(const unsigned*)&Ah[ar][2 * ct];
            ah[1] = *(const unsigned*)&Ah[ar + 8][2 * ct];
            ah[2] = *(const unsigned*)&Ah[ar][2 * ct + 8];
            ah[3] = *(const unsigned*)&Ah[ar + 8][2 * ct + 8];
#pragma unroll
            for (int nt = 0; nt < 8; nt++)
                MMA16816(d[mt][nt], ah, bh[nt]);
        }
        __syncthreads();
    }

    // ---- epilogue: scale by rsqrt(deg+1) read from g_deg, store fp16 ----
#pragma unroll
    for (int mt = 0; mt < 2; mt++) {
        int r1 = row0 + wm * 32 + mt * 16 + gr;
        int r2 = r1 + 8;
        float s1 = (r1 < N_NODES) ? rsqrtf((float)(g_deg[r1] + 1)) : 0.f;
        float s2 = (r2 < N_NODES) ? rsqrtf((float)(g_deg[r2] + 1)) : 0.f;
#pragma unroll
        for (int nt = 0; nt < 8; nt++) {
            int c = wn * 64 + nt * 8 + 2 * ct;
            if (r1 < N_NODES)
                *(__half2*)&g_y1h[(size_t)r1 * F1 + c] =
                    __floats2half2_rn(d[mt][nt][0] * s1, d[mt][nt][1] * s1);
            if (r2 < N_NODES)
                *(__half2*)&g_y1h[(size_t)r2 * F1 + c] =
                    __floats2half2_rn(d[mt][nt][2] * s2, d[mt][nt][3] * s2);
        }
    }
}

// ---------------- agg 1: h = relu(dinv[d]*(y1[d] + sum y1[src]) + b1) --------
// warp per node; unroll-8 gather for deeper MLP.
__global__ void k_agg1(const float* __restrict__ b) {
    int d = blockIdx.x * 8 + (threadIdx.x >> 5);
    if (d >= N_NODES) return;
    int lane = threadIdx.x & 31;
    const float2* Y = (const float2*)g_y1h;   // 32 float2 per row

    float ax[4] = {0.f, 0.f, 0.f, 0.f};
    {
        float2 r = __ldg(&Y[(size_t)d * 32 + lane]);  // self loop
        float2 f0 = __half22float2(*(__half2*)&r.x);
        float2 f1 = __half22float2(*(__half2*)&r.y);
        ax[0] = f0.x; ax[1] = f0.y; ax[2] = f1.x; ax[3] = f1.y;
    }
    float ay[4] = {0.f, 0.f, 0.f, 0.f};
    float az[4] = {0.f, 0.f, 0.f, 0.f};
    float aw[4] = {0.f, 0.f, 0.f, 0.f};

    int j = g_off[d], end = g_off[d + 1];
    for (; j + 8 <= end; j += 8) {
        int s0 = __ldg(&g_csr[j]),     s1 = __ldg(&g_csr[j + 1]);
        int s2 = __ldg(&g_csr[j + 2]), s3 = __ldg(&g_csr[j + 3]);
        int s4 = __ldg(&g_csr[j + 4]), s5 = __ldg(&g_csr[j + 5]);
        int s6 = __ldg(&g_csr[j + 6]), s7 = __ldg(&g_csr[j + 7]);
        float2 r0 = __ldg(&Y[(size_t)s0 * 32 + lane]);
        float2 r1 = __ldg(&Y[(size_t)s1 * 32 + lane]);
        float2 r2 = __ldg(&Y[(size_t)s2 * 32 + lane]);
        float2 r3 = __ldg(&Y[(size_t)s3 * 32 + lane]);
        float2 r4 = __ldg(&Y[(size_t)s4 * 32 + lane]);
        float2 r5 = __ldg(&Y[(size_t)s5 * 32 + lane]);
        float2 r6 = __ldg(&Y[(size_t)s6 * 32 + lane]);
        float2 r7 = __ldg(&Y[(size_t)s7 * 32 + lane]);
        float2 f;
        f = __half22float2(*(__half2*)&r0.x); ax[0] += f.x; ax[1] += f.y;
        f = __half22float2(*(__half2*)&r0.y); ax[2] += f.x; ax[3] += f.y;
        f = __half22float2(*(__half2*)&r1.x); ay[0] += f.x; ay[1] += f.y;
        f = __half22float2(*(__half2*)&r1.y); ay[2] += f.x; ay[3] += f.y;
        f = __half22float2(*(__half2*)&r2.x); az[0] += f.x; az[1] += f.y;
        f = __half22float2(*(__half2*)&r2.y); az[2] += f.x; az[3] += f.y;
        f = __half22float2(*(__half2*)&r3.x); aw[0] += f.x; aw[1] += f.y;
        f = __half22float2(*(__half2*)&r3.y); aw[2] += f.x; aw[3] += f.y;
        f = __half22float2(*(__half2*)&r4.x); ax[0] += f.x; ax[1] += f.y;
        f = __half22float2(*(__half2*)&r4.y); ax[2] += f.x; ax[3] += f.y;
        f = __half22float2(*(__half2*)&r5.x); ay[0] += f.x; ay[1] += f.y;
        f = __half22float2(*(__half2*)&r5.y); ay[2] += f.x; ay[3] += f.y;
        f = __half22float2(*(__half2*)&r6.x); az[0] += f.x; az[1] += f.y;
        f = __half22float2(*(__half2*)&r6.y); az[2] += f.x; az[3] += f.y;
        f = __half22float2(*(__half2*)&r7.x); aw[0] += f.x; aw[1] += f.y;
        f = __half22float2(*(__half2*)&r7.y); aw[2] += f.x; aw[3] += f.y;
    }
    for (; j < end; j++) {
        float2 r = __ldg(&Y[(size_t)__ldg(&g_csr[j]) * 32 + lane]);
        float2 f;
        f = __half22float2(*(__half2*)&r.x); ax[0] += f.x; ax[1] += f.y;
        f = __half22float2(*(__half2*)&r.y); ax[2] += f.x; ax[3] += f.y;
    }
#pragma unroll
    for (int i = 0; i < 4; i++) ax[i] += ay[i] + az[i] + aw[i];

    float s = g_dinv[d];
    float4 bb = ((const float4*)b)[lane];
    float o[4];
    o[0] = fmaxf(fmaf(ax[0], s, bb.x), 0.f);
    o[1] = fmaxf(fmaf(ax[1], s, bb.y), 0.f);
    o[2] = fmaxf(fmaf(ax[2], s, bb.z), 0.f);
    o[3] = fmaxf(fmaf(ax[3], s, bb.w), 0.f);
    __half2 p0 = __floats2half2_rn(o[0], o[1]);
    __half2 p1 = __floats2half2_rn(o[2], o[3]);
    float2 pk;
    pk.x = __uint_as_float(*(unsigned*)&p0);
    pk.y = __uint_as_float(*(unsigned*)&p1);
    *(float2*)&g_hh[(size_t)d * F1 + lane * 4] = pk;
}

// ---------------- GEMM 2 (single fp16 HMMA): y2h = half(dinv*(h@W2)) --------
// BM=128, BN=64, BK=16; 8 warps 4(M)x2(N); warp tile 32x32.
__global__ __launch_bounds__(256) void k_gemm2() {
    __shared__ __half Ah[128][18];
    __shared__ __half Bh[64][18];

    const int tid  = threadIdx.x;
    const int warp = tid >> 5, lane = tid & 31;
    const int wm = warp >> 1, wn = warp & 1;
    const int gr = lane >> 2, ct = lane & 3;
    const int row0 = blockIdx.x * 128;

    float d[2][4][4];
#pragma unroll
    for (int mt = 0; mt < 2; mt++)
#pragma unroll
        for (int nt = 0; nt < 4; nt++)
#pragma unroll
            for (int j = 0; j < 4; j++) d[mt][nt][j] = 0.f;

    const unsigned* HH = (const unsigned*)g_hh;      // [node][64] u32
    const unsigned* WT = (const unsigned*)g_W2T;     // [64][64] u32

    for (int kt = 0; kt < F1 / 16; kt++) {
        int k0 = kt * 16;
        // ---- A tile 128x16: direct u32 copies (already fp16) ----
        {
            int r = tid >> 1;
            int w0 = (tid & 1) * 4;
            int grow = row0 + r;
            unsigned* dh = (unsigned*)Ah;
            if (grow < N_NODES) {
                size_t src = (size_t)grow * 64 + (k0 >> 1) + w0;
#pragma unroll
                for (int i = 0; i < 4; i++)
                    dh[r * 9 + w0 + i] = HH[src + i];
            } else {
#pragma unroll
                for (int i = 0; i < 4; i++)
                    dh[r * 9 + w0 + i] = 0u;
            }
        }
        // ---- B tile: 64 rows x 8 u32 ----
        {
            unsigned* dh = (unsigned*)Bh;
#pragma unroll
            for (int i = 0; i < 2; i++) {
                int idx = tid + i * 256;          // 0..511
                int n = idx >> 3, w = idx & 7;
                dh[n * 9 + w] = WT[n * (F1 / 2) + (k0 >> 1) + w];
            }
        }
        __syncthreads();

        unsigned bh[4][2];
#pragma unroll
        for (int nt = 0; nt < 4; nt++) {
            int nn = wn * 32 + nt * 8 + gr;
            bh[nt][0] = *(const unsigned*)&Bh[nn][2 * ct];
            bh[nt][1] = *(const unsigned*)&Bh[nn][2 * ct + 8];
        }
#pragma unroll
        for (int mt = 0; mt < 2; mt++) {
            int ar = wm * 32 + mt * 16 + gr;
            unsigned ah[4];
            ah[0] = *(const unsigned*)&Ah[ar][2 * ct];
            ah[1] = *(const unsigned*)&Ah[ar + 8][2 * ct];
            ah[2] = *(const unsigned*)&Ah[ar][2 * ct + 8];
            ah[3] = *(const unsigned*)&Ah[ar + 8][2 * ct + 8];
#pragma unroll
            for (int nt = 0; nt < 4; nt++)
                MMA16816(d[mt][nt], ah, bh[nt]);
        }
        __syncthreads();
    }

#pragma unroll
    for (int mt = 0; mt < 2; mt++) {
        int r1 = row0 + wm * 32 + mt * 16 + gr;
        int r2 = r1 + 8;
        float s1 = (r1 < N_NODES) ? g_dinv[r1] : 0.f;
        float s2 = (r2 < N_NODES) ? g_dinv[r2] : 0.f;
#pragma unroll
        for (int nt = 0; nt < 4; nt++) {
            int c = wn * 32 + nt * 8 + 2 * ct;
            if (r1 < N_NODES)
                *(__half2*)&g_y2h[(size_t)r1 * F2 + c] =
                    __floats2half2_rn(d[mt][nt][0] * s1, d[mt][nt][1] * s1);
            if (r2 < N_NODES)
                *(__half2*)&g_y2h[(size_t)r2 * F2 + c] =
                    __floats2half2_rn(d[mt][nt][2] * s2, d[mt][nt][3] * s2);
        }
    }
}

// ---------------- agg 2: out = dinv[d]*(y2[d] + sum y2[src]) + b2 ----------------
// warp per node; unroll-8 gather.
__global__ void k_agg2(const float* __restrict__ b, float* __restrict__ out) {
    int d = blockIdx.x * 8 + (threadIdx.x >> 5);
    if (d >= N_NODES) return;
    int lane = threadIdx.x & 31;
    const __half2* Y = (const __half2*)g_y2h;   // 32 half2 per row

    float2 a0 = __half22float2(__ldg(&Y[(size_t)d * 32 + lane]));  // self loop
    float2 a1 = make_float2(0.f, 0.f);
    float2 a2 = make_float2(0.f, 0.f);
    float2 a3 = make_float2(0.f, 0.f);

    int j = g_off[d], end = g_off[d + 1];
    for (; j + 8 <= end; j += 8) {
        int s0 = __ldg(&g_csr[j]),     s1 = __ldg(&g_csr[j + 1]);
        int s2 = __ldg(&g_csr[j + 2]), s3 = __ldg(&g_csr[j + 3]);
        int s4 = __ldg(&g_csr[j + 4]), s5 = __ldg(&g_csr[j + 5]);
        int s6 = __ldg(&g_csr[j + 6]), s7 = __ldg(&g_csr[j + 7]);
        float2 v0 = __half22float2(__ldg(&Y[(size_t)s0 * 32 + lane]));
        float2 v1 = __half22float2(__ldg(&Y[(size_t)s1 * 32 + lane]));
        float2 v2 = __half22float2(__ldg(&Y[(size_t)s2 * 32 + lane]));
        float2 v3 = __half22float2(__ldg(&Y[(size_t)s3 * 32 + lane]));
        float2 v4 = __half22float2(__ldg(&Y[(size_t)s4 * 32 + lane]));
        float2 v5 = __half22float2(__ldg(&Y[(size_t)s5 * 32 + lane]));
        float2 v6 = __half22float2(__ldg(&Y[(size_t)s6 * 32 + lane]));
        float2 v7 = __half22float2(__ldg(&Y[(size_t)s7 * 32 + lane]));
        a0.x += v0.x + v4.x; a0.y += v0.y + v4.y;
        a1.x += v1.x + v5.x; a1.y += v1.y + v5.y;
        a2.x += v2.x + v6.x; a2.y += v2.y + v6.y;
        a3.x += v3.x + v7.x; a3.y += v3.y + v7.y;
    }
    for (; j < end; j++) {
        float2 v = __half22float2(__ldg(&Y[(size_t)__ldg(&g_csr[j]) * 32 + lane]));
        a0.x += v.x; a0.y += v.y;
    }
    float2 acc = make_float2(a0.x + a1.x + a2.x + a3.x,
                             a0.y + a1.y + a2.y + a3.y);
    float s = g_dinv[d];
    float2 bb = ((const float2*)b)[lane];
    acc.x = fmaf(acc.x, s, bb.x);
    acc.y = fmaf(acc.y, s, bb.y);
    ((float2*)out)[(size_t)d * 32 + lane] = acc;
}

extern "C" void kernel_launch(void* const* d_in, const int* in_sizes, int n_in,
                              void* d_out, int out_size) {
    const float* x   = (const float*)d_in[0];
    const int*   ei  = (const int*)d_in[1];
    const float* W1  = (const float*)d_in[2];
    const float* b1  = (const float*)d_in[3];
    const float* W2  = (const float*)d_in[4];
    const float* b2  = (const float*)d_in[5];
    float*       out = (float*)d_out;

    const int* src = ei;
    const int* dst = ei + N_EDGES;

    // ---- branch C: weight conversion (independent of everything else) ----
    cudaEventRecord(ev_root, 0);
    cudaStreamWaitEvent(s_conv, ev_root, 0);
    k_convW1<<<(F1 * F0P + 255) / 256, 256, 0, s_conv>>>(W1);
    k_convW2<<<(F2 * F1 + 255) / 256, 256, 0, s_conv>>>(W2);
    cudaEventRecord(ev_conv, s_conv);

    // ---- main stream: degree ----
    k_zero_deg<<<(N_NODES + 255) / 256, 256>>>();
    k_count<<<(N_EDGES + 255) / 256, 256>>>(dst);

    // ---- branch B: CSR build (scan + fill), concurrent with gemm1 ----
    cudaEventRecord(ev_cnt, 0);
    cudaStreamWaitEvent(s_csr, ev_cnt, 0);
    k_scan1<<<N_SCANBLK, SCAN_B, 0, s_csr>>>();   // also writes g_dinv
    k_scan2<<<1, 128, 0, s_csr>>>();
    k_scan3<<<N_SCANBLK, SCAN_B, 0, s_csr>>>();
    k_fill<<<(N_EDGES + 255) / 256, 256, 0, s_csr>>>(src, dst);
    cudaEventRecord(ev_csr, s_csr);

    // ---- main stream: gemm1 (waits on weights; dinv from g_deg in-epilogue) ----
    cudaStreamWaitEvent(0, ev_conv, 0);
    k_gemm1<<<(N_NODES + 127) / 128, 256>>>(x);

    // ---- join CSR branch, then aggregate + layer 2 ----
    cudaStreamWaitEvent(0, ev_csr, 0);
    k_agg1<<<(N_NODES + 7) / 8, 256>>>(b1);
    k_gemm2<<<(N_NODES + 127) / 128, 256>>>();
    k_agg2<<<(N_NODES + 7) / 8, 256>>>(b2, out);
}